// round 4
// baseline (speedup 1.0000x reference)
#include <cuda_runtime.h>
#include <cstdint>

#define S_LEN   4096
#define DMODEL  1024
#define NHEADS  16
#define DK      64

// Scratch (allocation-free rule: __device__ globals)
__device__ float g_q [S_LEN * DMODEL];
__device__ float g_k [S_LEN * DMODEL];
__device__ float g_v [S_LEN * DMODEL];
__device__ float g_ao[S_LEN * DMODEL];

// ---------------------------------------------------------------------------
// tf32 helpers
// ---------------------------------------------------------------------------
__device__ __forceinline__ float f2tf(float f) {
    uint32_t r;
    asm("cvt.rna.tf32.f32 %0, %1;" : "=r"(r) : "f"(f));
    return __uint_as_float(r);
}

// D += A(16x8) * B(8x8), tf32 inputs, fp32 accum
__device__ __forceinline__ void mma8(float* d, const uint32_t* a, const uint32_t* b) {
    asm volatile(
        "mma.sync.aligned.m16n8k8.row.col.f32.tf32.tf32.f32 "
        "{%0,%1,%2,%3}, {%4,%5,%6,%7}, {%8,%9}, {%0,%1,%2,%3};"
        : "+f"(d[0]), "+f"(d[1]), "+f"(d[2]), "+f"(d[3])
        : "r"(a[0]), "r"(a[1]), "r"(a[2]), "r"(a[3]), "r"(b[0]), "r"(b[1]));
}

// ---------------------------------------------------------------------------
// NT GEMM (tf32 tensor cores): C[M,N] = A[M,K] * B[N,K]^T
// Block 128x128x32, 8 warps as 2(m) x 4(n), warp tile 64x32.  (unchanged)
// ---------------------------------------------------------------------------
#define GBM 128
#define GBN 128
#define GBK 32
#define GLD (GBK + 4)

__global__ void __launch_bounds__(256) gemm_nt_tf32(const float* __restrict__ A,
                                                    const float* __restrict__ B,
                                                    float* __restrict__ C,
                                                    int M, int N, int K) {
    __shared__ float As[GBM][GLD];
    __shared__ float Bs[GBN][GLD];

    const int tid  = threadIdx.x;
    const int warp = tid >> 5, lane = tid & 31;
    const int wm   = warp >> 2;
    const int wn   = warp & 3;
    const int g    = lane >> 2;
    const int tg   = lane & 3;
    const int bm   = blockIdx.y * GBM;
    const int bn   = blockIdx.x * GBN;

    const int lrow = tid >> 3;
    const int lc   = (tid & 7) * 4;

    float acc[4][4][4];
#pragma unroll
    for (int mt = 0; mt < 4; mt++)
#pragma unroll
        for (int nt = 0; nt < 4; nt++)
#pragma unroll
            for (int i = 0; i < 4; i++) acc[mt][nt][i] = 0.f;

    for (int k0 = 0; k0 < K; k0 += GBK) {
#pragma unroll
        for (int p = 0; p < 4; p++) {
            int r = lrow + p * 32;
            float4 a4 = *(const float4*)(A + (size_t)(bm + r) * K + k0 + lc);
            float4 b4 = *(const float4*)(B + (size_t)(bn + r) * K + k0 + lc);
            *(float4*)&As[r][lc] = make_float4(f2tf(a4.x), f2tf(a4.y), f2tf(a4.z), f2tf(a4.w));
            *(float4*)&Bs[r][lc] = make_float4(f2tf(b4.x), f2tf(b4.y), f2tf(b4.z), f2tf(b4.w));
        }
        __syncthreads();

#pragma unroll
        for (int ks = 0; ks < GBK / 8; ks++) {
            const int kb = ks * 8;
            uint32_t af[4][4], bf[4][2];
#pragma unroll
            for (int mt = 0; mt < 4; mt++) {
                int r = wm * 64 + mt * 16 + g;
                af[mt][0] = __float_as_uint(As[r    ][kb + tg]);
                af[mt][1] = __float_as_uint(As[r + 8][kb + tg]);
                af[mt][2] = __float_as_uint(As[r    ][kb + tg + 4]);
                af[mt][3] = __float_as_uint(As[r + 8][kb + tg + 4]);
            }
#pragma unroll
            for (int nt = 0; nt < 4; nt++) {
                int c = wn * 32 + nt * 8 + g;
                bf[nt][0] = __float_as_uint(Bs[c][kb + tg]);
                bf[nt][1] = __float_as_uint(Bs[c][kb + tg + 4]);
            }
#pragma unroll
            for (int mt = 0; mt < 4; mt++)
#pragma unroll
                for (int nt = 0; nt < 4; nt++) mma8(acc[mt][nt], af[mt], bf[nt]);
        }
        __syncthreads();
    }

#pragma unroll
    for (int mt = 0; mt < 4; mt++)
#pragma unroll
        for (int nt = 0; nt < 4; nt++) {
            int r0 = bm + wm * 64 + mt * 16 + g;
            int c  = bn + wn * 32 + nt * 8 + 2 * tg;
            *(float2*)(C + (size_t)r0 * N + c)       = make_float2(acc[mt][nt][0], acc[mt][nt][1]);
            *(float2*)(C + (size_t)(r0 + 8) * N + c) = make_float2(acc[mt][nt][2], acc[mt][nt][3]);
        }
}

// ---------------------------------------------------------------------------
// Flash attention, tf32 mma, k-PERMUTED smem layouts for vector frag loads.
// K (and P, aliased) stored with col permutation p(c) = (c&7)*8 + (c>>3):
// a thread's mma fragment elements for all 8 k-steps become contiguous
// 8-float runs -> LDS.128 instead of scalar LDS.
// V stays natural [t][d] (coalesced loads, conflict-free scalar b-frags).
// ---------------------------------------------------------------------------
#define BQ 64
#define BT 64
#define KLD 68     // Ks/Ps row stride: frag-load start banks 4g+8tg, conflict-free
#define VLD 72     // Vs row stride: b-frag banks 8tg+g, conflict-free

__global__ void __launch_bounds__(256) attn_mma(const float* __restrict__ Qg,
                                                const float* __restrict__ Kg,
                                                const float* __restrict__ Vg,
                                                float* __restrict__ Og) {
    __shared__ __align__(16) float KsPs[BT][KLD];  // phase A: K permuted; phase B: P permuted
    __shared__ __align__(16) float Vs[BT][VLD];    // V natural [t][d]
    __shared__ float smax[BQ][2], ssum[BQ][2];

    const int h   = blockIdx.y;
    const int q0  = blockIdx.x * BQ;
    const int tid = threadIdx.x;
    const int warp = tid >> 5, lane = tid & 31;
    const int wm  = warp >> 1;         // 0..3 -> q rows [wm*16, wm*16+16)
    const int wn  = warp & 1;          // 0..1 -> kv/d cols [wn*32, wn*32+32)
    const int g   = lane >> 2;         // 0..7
    const int tg  = lane & 3;          // 0..3

    const int r0 = wm * 16 + g;
    const int r1 = r0 + 8;

    // ---- Persistent Q fragments (pre-scaled by 1/sqrt(dk)); logical k idx ----
    uint32_t qf[8][4];
    {
        const float* qp0 = Qg + (size_t)(q0 + r0) * DMODEL + h * DK;
        const float* qp1 = Qg + (size_t)(q0 + r1) * DMODEL + h * DK;
#pragma unroll
        for (int ks = 0; ks < 8; ks++) {
            int kc = ks * 8 + tg;
            qf[ks][0] = __float_as_uint(f2tf(qp0[kc]     * 0.125f));
            qf[ks][1] = __float_as_uint(f2tf(qp1[kc]     * 0.125f));
            qf[ks][2] = __float_as_uint(f2tf(qp0[kc + 4] * 0.125f));
            qf[ks][3] = __float_as_uint(f2tf(qp1[kc + 4] * 0.125f));
        }
    }

    // Store-side indices (hoisted): coalesced gmem mapping t=idx>>4, c4=(idx&15)*4
    const int ld_t  = tid >> 4;          // +16 per p-step
    const int ld_c4 = (tid & 15) * 4;
    const int kj0   = (ld_c4 & 7) * 8 + (ld_c4 >> 3);  // permuted base for K stores

    float m0 = -1e30f, m1 = -1e30f, l0 = 0.f, l1 = 0.f;
    float oacc[4][4];
#pragma unroll
    for (int nt = 0; nt < 4; nt++)
#pragma unroll
        for (int i = 0; i < 4; i++) oacc[nt][i] = 0.f;

    for (int t0 = 0; t0 < S_LEN; t0 += BT) {
        __syncthreads();   // prev tile's P/V reads done before overwrite

        // ---- K tile: coalesced load, PERMUTED scalar stores ----
#pragma unroll
        for (int p = 0; p < 4; p++) {
            int t = ld_t + p * 16;
            float4 k4 = *(const float4*)(Kg + (size_t)(t0 + t) * DMODEL + h * DK + ld_c4);
            KsPs[t][kj0     ] = f2tf(k4.x);
            KsPs[t][kj0 +  8] = f2tf(k4.y);
            KsPs[t][kj0 + 16] = f2tf(k4.z);
            KsPs[t][kj0 + 24] = f2tf(k4.w);
        }
        // ---- V tile: natural layout, STS.128 ----
#pragma unroll
        for (int p = 0; p < 4; p++) {
            int t = ld_t + p * 16;
            float4 v4 = *(const float4*)(Vg + (size_t)(t0 + t) * DMODEL + h * DK + ld_c4);
            *(float4*)&Vs[t][ld_c4] = make_float4(f2tf(v4.x), f2tf(v4.y), f2tf(v4.z), f2tf(v4.w));
        }
        __syncthreads();

        // ---- S = (Q/8) K^T : b-frags via 4x LDS.128 per nt (all 8 ks) ----
        float accS[4][4];
#pragma unroll
        for (int nt = 0; nt < 4; nt++)
#pragma unroll
            for (int i = 0; i < 4; i++) accS[nt][i] = 0.f;

#pragma unroll
        for (int nt = 0; nt < 4; nt++) {
            const int trow = wn * 32 + nt * 8 + g;
            float bv0[8], bv1[8];
            *(float4*)&bv0[0] = *(const float4*)&KsPs[trow][tg * 8];
            *(float4*)&bv0[4] = *(const float4*)&KsPs[trow][tg * 8 + 4];
            *(float4*)&bv1[0] = *(const float4*)&KsPs[trow][(tg + 4) * 8];
            *(float4*)&bv1[4] = *(const float4*)&KsPs[trow][(tg + 4) * 8 + 4];
#pragma unroll
            for (int ks = 0; ks < 8; ks++) {
                uint32_t b[2] = { __float_as_uint(bv0[ks]), __float_as_uint(bv1[ks]) };
                mma8(accS[nt], qf[ks], b);
            }
        }

        // ---- online softmax ----
        float mx0 = -1e30f, mx1 = -1e30f;
#pragma unroll
        for (int nt = 0; nt < 4; nt++) {
            mx0 = fmaxf(mx0, fmaxf(accS[nt][0], accS[nt][1]));
            mx1 = fmaxf(mx1, fmaxf(accS[nt][2], accS[nt][3]));
        }
        mx0 = fmaxf(mx0, __shfl_xor_sync(0xffffffffu, mx0, 1));
        mx0 = fmaxf(mx0, __shfl_xor_sync(0xffffffffu, mx0, 2));
        mx1 = fmaxf(mx1, __shfl_xor_sync(0xffffffffu, mx1, 1));
        mx1 = fmaxf(mx1, __shfl_xor_sync(0xffffffffu, mx1, 2));
        if (tg == 0) { smax[r0][wn] = mx0; smax[r1][wn] = mx1; }
        __syncthreads();   // all S-phase K reads done -> P may overwrite KsPs

        float mn0 = fmaxf(fmaxf(smax[r0][0], smax[r0][1]), m0);
        float mn1 = fmaxf(fmaxf(smax[r1][0], smax[r1][1]), m1);
        float c0 = __expf(m0 - mn0), c1 = __expf(m1 - mn1);
        m0 = mn0; m1 = mn1;

        // P written PERMUTED over t: t = wn*32+nt*8+2tg+b -> j = (2tg+b)*8 + 4wn+nt
        float ps0 = 0.f, ps1 = 0.f;
        {
            const int jb = 16 * tg + 4 * wn;
#pragma unroll
            for (int nt = 0; nt < 4; nt++) {
                float p00 = __expf(accS[nt][0] - m0);
                float p01 = __expf(accS[nt][1] - m0);
                float p10 = __expf(accS[nt][2] - m1);
                float p11 = __expf(accS[nt][3] - m1);
                ps0 += p00 + p01; ps1 += p10 + p11;
                KsPs[r0][jb + nt    ] = f2tf(p00);
                KsPs[r0][jb + nt + 8] = f2tf(p01);
                KsPs[r1][jb + nt    ] = f2tf(p10);
                KsPs[r1][jb + nt + 8] = f2tf(p11);
            }
        }
        ps0 += __shfl_xor_sync(0xffffffffu, ps0, 1);
        ps0 += __shfl_xor_sync(0xffffffffu, ps0, 2);
        ps1 += __shfl_xor_sync(0xffffffffu, ps1, 1);
        ps1 += __shfl_xor_sync(0xffffffffu, ps1, 2);
        if (tg == 0) { ssum[r0][wn] = ps0; ssum[r1][wn] = ps1; }
        __syncthreads();   // P + ssum visible

        l0 = l0 * c0 + ssum[r0][0] + ssum[r0][1];
        l1 = l1 * c1 + ssum[r1][0] + ssum[r1][1];
#pragma unroll
        for (int nt = 0; nt < 4; nt++) {
            oacc[nt][0] *= c0; oacc[nt][1] *= c0;
            oacc[nt][2] *= c1; oacc[nt][3] *= c1;
        }

        // ---- O += P V : a-frags via 8x LDS.128 (all 8 ks), V b-frags scalar ----
        float a0v[8], a1v[8], a2v[8], a3v[8];
        *(float4*)&a0v[0] = *(const float4*)&KsPs[r0][tg * 8];
        *(float4*)&a0v[4] = *(const float4*)&KsPs[r0][tg * 8 + 4];
        *(float4*)&a1v[0] = *(const float4*)&KsPs[r1][tg * 8];
        *(float4*)&a1v[4] = *(const float4*)&KsPs[r1][tg * 8 + 4];
        *(float4*)&a2v[0] = *(const float4*)&KsPs[r0][(tg + 4) * 8];
        *(float4*)&a2v[4] = *(const float4*)&KsPs[r0][(tg + 4) * 8 + 4];
        *(float4*)&a3v[0] = *(const float4*)&KsPs[r1][(tg + 4) * 8];
        *(float4*)&a3v[4] = *(const float4*)&KsPs[r1][(tg + 4) * 8 + 4];

#pragma unroll
        for (int nt = 0; nt < 4; nt++) {
            const int d = wn * 32 + nt * 8 + g;
#pragma unroll
            for (int ks = 0; ks < 8; ks++) {
                uint32_t a[4] = { __float_as_uint(a0v[ks]), __float_as_uint(a1v[ks]),
                                  __float_as_uint(a2v[ks]), __float_as_uint(a3v[ks]) };
                uint32_t b[2] = { __float_as_uint(Vs[ks * 8 + tg][d]),
                                  __float_as_uint(Vs[ks * 8 + tg + 4][d]) };
                mma8(oacc[nt], a, b);
            }
        }
    }

    // ---- normalize + write ----
    float inv0 = 1.f / l0, inv1 = 1.f / l1;
#pragma unroll
    for (int nt = 0; nt < 4; nt++) {
        int c = h * DK + wn * 32 + nt * 8 + 2 * tg;
        *(float2*)(Og + (size_t)(q0 + r0) * DMODEL + c) =
            make_float2(oacc[nt][0] * inv0, oacc[nt][1] * inv0);
        *(float2*)(Og + (size_t)(q0 + r1) * DMODEL + c) =
            make_float2(oacc[nt][2] * inv1, oacc[nt][3] * inv1);
    }
}

// ---------------------------------------------------------------------------
extern "C" void kernel_launch(void* const* d_in, const int* in_sizes, int n_in,
                              void* d_out, int out_size) {
    const float* x  = (const float*)d_in[0];
    const float* Wq = (const float*)d_in[1];
    const float* Wk = (const float*)d_in[2];
    const float* Wv = (const float*)d_in[3];
    const float* Wo = (const float*)d_in[4];
    float* out = (float*)d_out;

    float *q, *k, *v, *ao;
    cudaGetSymbolAddress((void**)&q,  g_q);
    cudaGetSymbolAddress((void**)&k,  g_k);
    cudaGetSymbolAddress((void**)&v,  g_v);
    cudaGetSymbolAddress((void**)&ao, g_ao);

    dim3 gg(DMODEL / GBN, S_LEN / GBM);  // (8, 32)
    gemm_nt_tf32<<<gg, 256>>>(x, Wq, q, S_LEN, DMODEL, DMODEL);
    gemm_nt_tf32<<<gg, 256>>>(x, Wk, k, S_LEN, DMODEL, DMODEL);
    gemm_nt_tf32<<<gg, 256>>>(x, Wv, v, S_LEN, DMODEL, DMODEL);

    attn_mma<<<dim3(S_LEN / BQ, NHEADS), 256>>>(q, k, v, ao);

    gemm_nt_tf32<<<gg, 256>>>(ao, Wo, out, S_LEN, DMODEL, DMODEL);
}

// round 5
// speedup vs baseline: 1.1802x; 1.1802x over previous
#include <cuda_runtime.h>
#include <cstdint>

#define S_LEN   4096
#define DMODEL  1024
#define NHEADS  16
#define DK      64

// Scratch (allocation-free rule: __device__ globals)
__device__ float g_q [S_LEN * DMODEL];
__device__ float g_k [S_LEN * DMODEL];
__device__ float g_v [S_LEN * DMODEL];
__device__ float g_ao[S_LEN * DMODEL];
__device__ float g_xr[S_LEN * DMODEL];          // tf32-rounded x
__device__ float g_wr[4][DMODEL * DMODEL];      // tf32-rounded Wq,Wk,Wv,Wo

// ---------------------------------------------------------------------------
// helpers
// ---------------------------------------------------------------------------
__device__ __forceinline__ float f2tf(float f) {
    uint32_t r;
    asm("cvt.rna.tf32.f32 %0, %1;" : "=r"(r) : "f"(f));
    return __uint_as_float(r);
}

__device__ __forceinline__ void mma8(float* d, const uint32_t* a, const uint32_t* b) {
    asm volatile(
        "mma.sync.aligned.m16n8k8.row.col.f32.tf32.tf32.f32 "
        "{%0,%1,%2,%3}, {%4,%5,%6,%7}, {%8,%9}, {%0,%1,%2,%3};"
        : "+f"(d[0]), "+f"(d[1]), "+f"(d[2]), "+f"(d[3])
        : "r"(a[0]), "r"(a[1]), "r"(a[2]), "r"(a[3]), "r"(b[0]), "r"(b[1]));
}

__device__ __forceinline__ void cpa16(uint32_t dst, const void* src) {
    asm volatile("cp.async.cg.shared.global [%0], [%1], 16;" :: "r"(dst), "l"(src));
}
#define CPA_COMMIT() asm volatile("cp.async.commit_group;")
#define CPA_WAIT0()  asm volatile("cp.async.wait_group 0;" ::: "memory")

// ---------------------------------------------------------------------------
// tf32 rounding pass (once per input array)
// ---------------------------------------------------------------------------
__global__ void __launch_bounds__(256) round4(const float* __restrict__ in,
                                              float* __restrict__ out, int n4) {
    int i = blockIdx.x * blockDim.x + threadIdx.x;
    if (i < n4) {
        float4 v = ((const float4*)in)[i];
        ((float4*)out)[i] = make_float4(f2tf(v.x), f2tf(v.y), f2tf(v.z), f2tf(v.w));
    }
}

// ---------------------------------------------------------------------------
// NT GEMM, cp.async double-buffered, inputs pre-rounded to tf32 (no cvt).
// Block 128x128x32, 8 warps as 2(m) x 4(n), warp tile 64x32.
// Dynamic smem: As[2][128][36] + Bs[2][128][36] = 73728 B.
// ---------------------------------------------------------------------------
#define GBM 128
#define GBN 128
#define GBK 32
#define GLD 36
#define GBUF (GBM * GLD)          // 4608 floats per buffer
#define GB_OFF (2 * GBUF)         // Bs base

template <bool ROUNDC>
__global__ void __launch_bounds__(256) gemm_nt_async(const float* __restrict__ A,
                                                     const float* __restrict__ B,
                                                     float* __restrict__ C,
                                                     int M, int N, int K) {
    extern __shared__ __align__(16) float sm[];
    const uint32_t sb = (uint32_t)__cvta_generic_to_shared(sm);

    const int tid  = threadIdx.x;
    const int warp = tid >> 5, lane = tid & 31;
    const int wm   = warp >> 2;
    const int wn   = warp & 3;
    const int g    = lane >> 2;
    const int tg   = lane & 3;
    const int bm   = blockIdx.y * GBM;
    const int bn   = blockIdx.x * GBN;

    const int lr  = tid >> 3;          // 0..31 (+32 per p)
    const int lc  = (tid & 7) * 4;     // 0..28

    auto issue = [&](int k0, int buf) {
#pragma unroll
        for (int p = 0; p < 4; p++) {
            int r = lr + p * 32;
            cpa16(sb + (buf * GBUF + r * GLD + lc) * 4,
                  A + (size_t)(bm + r) * K + k0 + lc);
            cpa16(sb + (GB_OFF + buf * GBUF + r * GLD + lc) * 4,
                  B + (size_t)(bn + r) * K + k0 + lc);
        }
        CPA_COMMIT();
    };

    float acc[4][4][4];
#pragma unroll
    for (int mt = 0; mt < 4; mt++)
#pragma unroll
        for (int nt = 0; nt < 4; nt++)
#pragma unroll
            for (int i = 0; i < 4; i++) acc[mt][nt][i] = 0.f;

    issue(0, 0);
    int buf = 0;

    for (int k0 = 0; k0 < K; k0 += GBK) {
        CPA_WAIT0();
        __syncthreads();
        if (k0 + GBK < K) issue(k0 + GBK, buf ^ 1);

        const float* As = sm + buf * GBUF;
        const float* Bs = sm + GB_OFF + buf * GBUF;

#pragma unroll
        for (int ks = 0; ks < GBK / 8; ks++) {
            const int kb = ks * 8;
            uint32_t af[4][4], bf[4][2];
#pragma unroll
            for (int mt = 0; mt < 4; mt++) {
                int r = wm * 64 + mt * 16 + g;
                af[mt][0] = __float_as_uint(As[r * GLD + kb + tg]);
                af[mt][1] = __float_as_uint(As[(r + 8) * GLD + kb + tg]);
                af[mt][2] = __float_as_uint(As[r * GLD + kb + tg + 4]);
                af[mt][3] = __float_as_uint(As[(r + 8) * GLD + kb + tg + 4]);
            }
#pragma unroll
            for (int nt = 0; nt < 4; nt++) {
                int c = wn * 32 + nt * 8 + g;
                bf[nt][0] = __float_as_uint(Bs[c * GLD + kb + tg]);
                bf[nt][1] = __float_as_uint(Bs[c * GLD + kb + tg + 4]);
            }
#pragma unroll
            for (int mt = 0; mt < 4; mt++)
#pragma unroll
                for (int nt = 0; nt < 4; nt++) mma8(acc[mt][nt], af[mt], bf[nt]);
        }
        buf ^= 1;
    }

#pragma unroll
    for (int mt = 0; mt < 4; mt++)
#pragma unroll
        for (int nt = 0; nt < 4; nt++) {
            int r0 = bm + wm * 64 + mt * 16 + g;
            int c  = bn + wn * 32 + nt * 8 + 2 * tg;
            float v0 = acc[mt][nt][0], v1 = acc[mt][nt][1];
            float v2 = acc[mt][nt][2], v3 = acc[mt][nt][3];
            if (ROUNDC) { v0 = f2tf(v0); v1 = f2tf(v1); v2 = f2tf(v2); v3 = f2tf(v3); }
            *(float2*)(C + (size_t)r0 * N + c)       = make_float2(v0, v1);
            *(float2*)(C + (size_t)(r0 + 8) * N + c) = make_float2(v2, v3);
        }
}

// ---------------------------------------------------------------------------
// Flash attention (R2 structure) + cp.async double-buffered K/V tiles.
// Inputs pre-rounded tf32 (no cvt in the loop). Output rounded for final GEMM.
// Dynamic smem: Ks[2][64][68] + Vs[2][64][72] + stats = 72704 B.
// ---------------------------------------------------------------------------
#define BQ 64
#define BT 64
#define KLD 68
#define VLD 72
#define KBUF (BT * KLD)            // 4352
#define VS_OFF (2 * KBUF)          // 8704
#define VBUF (BT * VLD)            // 4608
#define SM_OFF (VS_OFF + 2 * VBUF) // 17920: smax[64][2]
#define SS_OFF (SM_OFF + 128)      // ssum[64][2]

__global__ void __launch_bounds__(256) attn_mma(const float* __restrict__ Qg,
                                                const float* __restrict__ Kg,
                                                const float* __restrict__ Vg,
                                                float* __restrict__ Og) {
    extern __shared__ __align__(16) float sm[];
    const uint32_t sb = (uint32_t)__cvta_generic_to_shared(sm);

    const int h   = blockIdx.y;
    const int q0  = blockIdx.x * BQ;
    const int tid = threadIdx.x;
    const int warp = tid >> 5, lane = tid & 31;
    const int wm  = warp >> 1;
    const int wn  = warp & 1;
    const int g   = lane >> 2;
    const int tg  = lane & 3;
    const int hoff = h * DK;

    const int r0 = wm * 16 + g;
    const int r1 = r0 + 8;

    const int ld_t  = tid >> 4;        // +16 per p
    const int ld_c4 = (tid & 15) * 4;

    auto issue_kv = [&](int t0, int buf) {
#pragma unroll
        for (int p = 0; p < 4; p++) {
            int t = ld_t + p * 16;
            const float* kp = Kg + (size_t)(t0 + t) * DMODEL + hoff + ld_c4;
            const float* vp = Vg + (size_t)(t0 + t) * DMODEL + hoff + ld_c4;
            cpa16(sb + (buf * KBUF + t * KLD + ld_c4) * 4, kp);
            cpa16(sb + (VS_OFF + buf * VBUF + t * VLD + ld_c4) * 4, vp);
        }
        CPA_COMMIT();
    };

    issue_kv(0, 0);

    // ---- Persistent Q fragments (pre-scaled; q already tf32) ----
    uint32_t qf[8][4];
    {
        const float* qp0 = Qg + (size_t)(q0 + r0) * DMODEL + hoff;
        const float* qp1 = Qg + (size_t)(q0 + r1) * DMODEL + hoff;
#pragma unroll
        for (int ks = 0; ks < 8; ks++) {
            int kc = ks * 8 + tg;
            qf[ks][0] = __float_as_uint(qp0[kc]     * 0.125f);
            qf[ks][1] = __float_as_uint(qp1[kc]     * 0.125f);
            qf[ks][2] = __float_as_uint(qp0[kc + 4] * 0.125f);
            qf[ks][3] = __float_as_uint(qp1[kc + 4] * 0.125f);
        }
    }

    float m0 = -1e30f, m1 = -1e30f, l0 = 0.f, l1 = 0.f;
    float oacc[4][4];
#pragma unroll
    for (int nt = 0; nt < 4; nt++)
#pragma unroll
        for (int i = 0; i < 4; i++) oacc[nt][i] = 0.f;

    int buf = 0;
    for (int t0 = 0; t0 < S_LEN; t0 += BT) {
        CPA_WAIT0();
        __syncthreads();   // tile ready + all threads done with other buffer
        if (t0 + BT < S_LEN) issue_kv(t0 + BT, buf ^ 1);

        float* KsPs = sm + buf * KBUF;            // [t][KLD]; P overlays after S
        const float* Vs = sm + VS_OFF + buf * VBUF;  // [t][VLD]

        // ---- S = (Q/8) K^T : warp computes 16 x 32 ----
        float accS[4][4];
#pragma unroll
        for (int nt = 0; nt < 4; nt++)
#pragma unroll
            for (int i = 0; i < 4; i++) accS[nt][i] = 0.f;

#pragma unroll
        for (int ks = 0; ks < 8; ks++) {
            const int kb = ks * 8;
            uint32_t bf[4][2];
#pragma unroll
            for (int nt = 0; nt < 4; nt++) {
                int t = wn * 32 + nt * 8 + g;
                bf[nt][0] = __float_as_uint(KsPs[t * KLD + kb + tg]);
                bf[nt][1] = __float_as_uint(KsPs[t * KLD + kb + tg + 4]);
            }
#pragma unroll
            for (int nt = 0; nt < 4; nt++) mma8(accS[nt], qf[ks], bf[nt]);
        }

        // ---- online softmax ----
        float mx0 = -1e30f, mx1 = -1e30f;
#pragma unroll
        for (int nt = 0; nt < 4; nt++) {
            mx0 = fmaxf(mx0, fmaxf(accS[nt][0], accS[nt][1]));
            mx1 = fmaxf(mx1, fmaxf(accS[nt][2], accS[nt][3]));
        }
        mx0 = fmaxf(mx0, __shfl_xor_sync(0xffffffffu, mx0, 1));
        mx0 = fmaxf(mx0, __shfl_xor_sync(0xffffffffu, mx0, 2));
        mx1 = fmaxf(mx1, __shfl_xor_sync(0xffffffffu, mx1, 1));
        mx1 = fmaxf(mx1, __shfl_xor_sync(0xffffffffu, mx1, 2));
        if (tg == 0) { sm[SM_OFF + r0 * 2 + wn] = mx0; sm[SM_OFF + r1 * 2 + wn] = mx1; }
        __syncthreads();   // smax visible; all S-phase K reads done -> P may overwrite

        float mn0 = fmaxf(fmaxf(sm[SM_OFF + r0 * 2], sm[SM_OFF + r0 * 2 + 1]), m0);
        float mn1 = fmaxf(fmaxf(sm[SM_OFF + r1 * 2], sm[SM_OFF + r1 * 2 + 1]), m1);
        float c0 = __expf(m0 - mn0), c1 = __expf(m1 - mn1);
        m0 = mn0; m1 = mn1;

        float ps0 = 0.f, ps1 = 0.f;
#pragma unroll
        for (int nt = 0; nt < 4; nt++) {
            int c = wn * 32 + nt * 8 + 2 * tg;
            float p00 = __expf(accS[nt][0] - m0);
            float p01 = __expf(accS[nt][1] - m0);
            float p10 = __expf(accS[nt][2] - m1);
            float p11 = __expf(accS[nt][3] - m1);
            ps0 += p00 + p01; ps1 += p10 + p11;
            *(float2*)&KsPs[r0 * KLD + c] = make_float2(f2tf(p00), f2tf(p01));
            *(float2*)&KsPs[r1 * KLD + c] = make_float2(f2tf(p10), f2tf(p11));
        }
        ps0 += __shfl_xor_sync(0xffffffffu, ps0, 1);
        ps0 += __shfl_xor_sync(0xffffffffu, ps0, 2);
        ps1 += __shfl_xor_sync(0xffffffffu, ps1, 1);
        ps1 += __shfl_xor_sync(0xffffffffu, ps1, 2);
        if (tg == 0) { sm[SS_OFF + r0 * 2 + wn] = ps0; sm[SS_OFF + r1 * 2 + wn] = ps1; }
        __syncthreads();   // P + ssum visible

        l0 = l0 * c0 + sm[SS_OFF + r0 * 2] + sm[SS_OFF + r0 * 2 + 1];
        l1 = l1 * c1 + sm[SS_OFF + r1 * 2] + sm[SS_OFF + r1 * 2 + 1];
#pragma unroll
        for (int nt = 0; nt < 4; nt++) {
            oacc[nt][0] *= c0; oacc[nt][1] *= c0;
            oacc[nt][2] *= c1; oacc[nt][3] *= c1;
        }

        // ---- O += P V ----
#pragma unroll
        for (int ks = 0; ks < 8; ks++) {
            const int kb = ks * 8;
            uint32_t af[4], bf[4][2];
            af[0] = __float_as_uint(KsPs[r0 * KLD + kb + tg]);
            af[1] = __float_as_uint(KsPs[r1 * KLD + kb + tg]);
            af[2] = __float_as_uint(KsPs[r0 * KLD + kb + tg + 4]);
            af[3] = __float_as_uint(KsPs[r1 * KLD + kb + tg + 4]);
#pragma unroll
            for (int nt = 0; nt < 4; nt++) {
                int d = wn * 32 + nt * 8 + g;
                bf[nt][0] = __float_as_uint(Vs[(kb + tg) * VLD + d]);
                bf[nt][1] = __float_as_uint(Vs[(kb + tg + 4) * VLD + d]);
            }
#pragma unroll
            for (int nt = 0; nt < 4; nt++) mma8(oacc[nt], af, bf[nt]);
        }
        buf ^= 1;
    }

    // ---- normalize + write (rounded: final GEMM consumes cvt-free) ----
    float inv0 = 1.f / l0, inv1 = 1.f / l1;
#pragma unroll
    for (int nt = 0; nt < 4; nt++) {
        int c = hoff + wn * 32 + nt * 8 + 2 * tg;
        *(float2*)(Og + (size_t)(q0 + r0) * DMODEL + c) =
            make_float2(f2tf(oacc[nt][0] * inv0), f2tf(oacc[nt][1] * inv0));
        *(float2*)(Og + (size_t)(q0 + r1) * DMODEL + c) =
            make_float2(f2tf(oacc[nt][2] * inv1), f2tf(oacc[nt][3] * inv1));
    }
}

// ---------------------------------------------------------------------------
extern "C" void kernel_launch(void* const* d_in, const int* in_sizes, int n_in,
                              void* d_out, int out_size) {
    const float* x  = (const float*)d_in[0];
    const float* Wq = (const float*)d_in[1];
    const float* Wk = (const float*)d_in[2];
    const float* Wv = (const float*)d_in[3];
    const float* Wo = (const float*)d_in[4];
    float* out = (float*)d_out;

    float *q, *k, *v, *ao, *xr, *wr;
    cudaGetSymbolAddress((void**)&q,  g_q);
    cudaGetSymbolAddress((void**)&k,  g_k);
    cudaGetSymbolAddress((void**)&v,  g_v);
    cudaGetSymbolAddress((void**)&ao, g_ao);
    cudaGetSymbolAddress((void**)&xr, g_xr);
    cudaGetSymbolAddress((void**)&wr, g_wr);
    float* wqr = wr;
    float* wkr = wr + (size_t)DMODEL * DMODEL;
    float* wvr = wr + (size_t)2 * DMODEL * DMODEL;
    float* wor = wr + (size_t)3 * DMODEL * DMODEL;

    const int GSM = 4 * GBM * GLD * sizeof(float);              // 73728
    const int ASM = (SS_OFF + 128) * sizeof(float);             // 72704
    cudaFuncSetAttribute(gemm_nt_async<true>,
                         cudaFuncAttributeMaxDynamicSharedMemorySize, GSM);
    cudaFuncSetAttribute(gemm_nt_async<false>,
                         cudaFuncAttributeMaxDynamicSharedMemorySize, GSM);
    cudaFuncSetAttribute(attn_mma,
                         cudaFuncAttributeMaxDynamicSharedMemorySize, ASM);

    // tf32-round inputs once
    round4<<<(S_LEN * DMODEL / 4 + 255) / 256, 256>>>(x,  xr,  S_LEN * DMODEL / 4);
    round4<<<(DMODEL * DMODEL / 4 + 255) / 256, 256>>>(Wq, wqr, DMODEL * DMODEL / 4);
    round4<<<(DMODEL * DMODEL / 4 + 255) / 256, 256>>>(Wk, wkr, DMODEL * DMODEL / 4);
    round4<<<(DMODEL * DMODEL / 4 + 255) / 256, 256>>>(Wv, wvr, DMODEL * DMODEL / 4);
    round4<<<(DMODEL * DMODEL / 4 + 255) / 256, 256>>>(Wo, wor, DMODEL * DMODEL / 4);

    dim3 gg(DMODEL / GBN, S_LEN / GBM);  // (8, 32)
    gemm_nt_async<true><<<gg, 256, GSM>>>(xr, wqr, q, S_LEN, DMODEL, DMODEL);
    gemm_nt_async<true><<<gg, 256, GSM>>>(xr, wkr, k, S_LEN, DMODEL, DMODEL);
    gemm_nt_async<true><<<gg, 256, GSM>>>(xr, wvr, v, S_LEN, DMODEL, DMODEL);

    attn_mma<<<dim3(S_LEN / BQ, NHEADS), 256, ASM>>>(q, k, v, ao);

    gemm_nt_async<false><<<gg, 256, GSM>>>(ao, wor, out, S_LEN, DMODEL, DMODEL);
}

// round 7
// speedup vs baseline: 1.2742x; 1.0797x over previous
#include <cuda_runtime.h>
#include <cstdint>

#define S_LEN   4096
#define DMODEL  1024
#define NHEADS  16
#define DK      64

// Scratch (allocation-free rule: __device__ globals)
__device__ float g_q [S_LEN * DMODEL];
__device__ float g_k [S_LEN * DMODEL];
__device__ float g_v [S_LEN * DMODEL];
__device__ float g_ao[S_LEN * DMODEL];
__device__ float g_xr[S_LEN * DMODEL];          // tf32-rounded x
__device__ float g_wr[4][DMODEL * DMODEL];      // tf32-rounded Wq,Wk,Wv,Wo

// ---------------------------------------------------------------------------
// helpers
// ---------------------------------------------------------------------------
__device__ __forceinline__ float f2tf(float f) {
    uint32_t r;
    asm("cvt.rna.tf32.f32 %0, %1;" : "=r"(r) : "f"(f));
    return __uint_as_float(r);
}

__device__ __forceinline__ void mma8(float* d, const uint32_t* a, const uint32_t* b) {
    asm volatile(
        "mma.sync.aligned.m16n8k8.row.col.f32.tf32.tf32.f32 "
        "{%0,%1,%2,%3}, {%4,%5,%6,%7}, {%8,%9}, {%0,%1,%2,%3};"
        : "+f"(d[0]), "+f"(d[1]), "+f"(d[2]), "+f"(d[3])
        : "r"(a[0]), "r"(a[1]), "r"(a[2]), "r"(a[3]), "r"(b[0]), "r"(b[1]));
}

__device__ __forceinline__ void cpa16(uint32_t dst, const void* src) {
    asm volatile("cp.async.cg.shared.global [%0], [%1], 16;" :: "r"(dst), "l"(src));
}
#define CPA_COMMIT() asm volatile("cp.async.commit_group;")
#define CPA_WAIT0()  asm volatile("cp.async.wait_group 0;" ::: "memory")

// ---------------------------------------------------------------------------
// tf32 rounding pass (once per input array)
// ---------------------------------------------------------------------------
__global__ void __launch_bounds__(256) round4(const float* __restrict__ in,
                                              float* __restrict__ out, int n4) {
    int i = blockIdx.x * blockDim.x + threadIdx.x;
    if (i < n4) {
        float4 v = ((const float4*)in)[i];
        ((float4*)out)[i] = make_float4(f2tf(v.x), f2tf(v.y), f2tf(v.z), f2tf(v.w));
    }
}

// ---------------------------------------------------------------------------
// NT GEMM, cp.async double-buffered, inputs pre-rounded to tf32 (no cvt).
// Block 128x128x32, 8 warps as 2(m) x 4(n), warp tile 64x32.  (R5 winner)
// ---------------------------------------------------------------------------
#define GBM 128
#define GBN 128
#define GBK 32
#define GLD 36
#define GBUF (GBM * GLD)
#define GB_OFF (2 * GBUF)

template <bool ROUNDC>
__global__ void __launch_bounds__(256) gemm_nt_async(const float* __restrict__ A,
                                                     const float* __restrict__ B,
                                                     float* __restrict__ C,
                                                     int M, int N, int K) {
    extern __shared__ __align__(16) float sm[];
    const uint32_t sb = (uint32_t)__cvta_generic_to_shared(sm);

    const int tid  = threadIdx.x;
    const int warp = tid >> 5, lane = tid & 31;
    const int wm   = warp >> 2;
    const int wn   = warp & 3;
    const int g    = lane >> 2;
    const int tg   = lane & 3;
    const int bm   = blockIdx.y * GBM;
    const int bn   = blockIdx.x * GBN;

    const int lr  = tid >> 3;
    const int lc  = (tid & 7) * 4;

    auto issue = [&](int k0, int buf) {
#pragma unroll
        for (int p = 0; p < 4; p++) {
            int r = lr + p * 32;
            cpa16(sb + (buf * GBUF + r * GLD + lc) * 4,
                  A + (size_t)(bm + r) * K + k0 + lc);
            cpa16(sb + (GB_OFF + buf * GBUF + r * GLD + lc) * 4,
                  B + (size_t)(bn + r) * K + k0 + lc);
        }
        CPA_COMMIT();
    };

    float acc[4][4][4];
#pragma unroll
    for (int mt = 0; mt < 4; mt++)
#pragma unroll
        for (int nt = 0; nt < 4; nt++)
#pragma unroll
            for (int i = 0; i < 4; i++) acc[mt][nt][i] = 0.f;

    issue(0, 0);
    int buf = 0;

    for (int k0 = 0; k0 < K; k0 += GBK) {
        CPA_WAIT0();
        __syncthreads();
        if (k0 + GBK < K) issue(k0 + GBK, buf ^ 1);

        const float* As = sm + buf * GBUF;
        const float* Bs = sm + GB_OFF + buf * GBUF;

#pragma unroll
        for (int ks = 0; ks < GBK / 8; ks++) {
            const int kb = ks * 8;
            uint32_t af[4][4], bf[4][2];
#pragma unroll
            for (int mt = 0; mt < 4; mt++) {
                int r = wm * 64 + mt * 16 + g;
                af[mt][0] = __float_as_uint(As[r * GLD + kb + tg]);
                af[mt][1] = __float_as_uint(As[(r + 8) * GLD + kb + tg]);
                af[mt][2] = __float_as_uint(As[r * GLD + kb + tg + 4]);
                af[mt][3] = __float_as_uint(As[(r + 8) * GLD + kb + tg + 4]);
            }
#pragma unroll
            for (int nt = 0; nt < 4; nt++) {
                int c = wn * 32 + nt * 8 + g;
                bf[nt][0] = __float_as_uint(Bs[c * GLD + kb + tg]);
                bf[nt][1] = __float_as_uint(Bs[c * GLD + kb + tg + 4]);
            }
#pragma unroll
            for (int mt = 0; mt < 4; mt++)
#pragma unroll
                for (int nt = 0; nt < 4; nt++) mma8(acc[mt][nt], af[mt], bf[nt]);
        }
        buf ^= 1;
    }

#pragma unroll
    for (int mt = 0; mt < 4; mt++)
#pragma unroll
        for (int nt = 0; nt < 4; nt++) {
            int r0 = bm + wm * 64 + mt * 16 + g;
            int c  = bn + wn * 32 + nt * 8 + 2 * tg;
            float v0 = acc[mt][nt][0], v1 = acc[mt][nt][1];
            float v2 = acc[mt][nt][2], v3 = acc[mt][nt][3];
            if (ROUNDC) { v0 = f2tf(v0); v1 = f2tf(v1); v2 = f2tf(v2); v3 = f2tf(v3); }
            *(float2*)(C + (size_t)r0 * N + c)       = make_float2(v0, v1);
            *(float2*)(C + (size_t)(r0 + 8) * N + c) = make_float2(v2, v3);
        }
}

// ---------------------------------------------------------------------------
// Flash attention v3: warp-owns-full-rows.
// 8 warps; warp w computes q-rows [w*16, w*16+16) x ALL 64 kv cols.
//   -> softmax stats fully in-warp (2 shuffles), NO cross-warp exchange,
//   -> P in warp-private smem (syncwarp only),
//   -> exactly ONE __syncthreads per kv tile (double-buffer swap),
//   -> BQ=128: one K/V tile serves 2x queries vs R5.
// ---------------------------------------------------------------------------
#define BQ 128
#define BT 64
#define KLD 68
#define VLD 72
#define PLD 68
#define KBUF (BT * KLD)                 // 4352 floats per K buffer
#define VS_OFF (2 * KBUF)               // 8704
#define VBUF (BT * VLD)                 // 4608
#define PS_OFF (VS_OFF + 2 * VBUF)      // 17920
#define PWARP (16 * PLD)                // 1088 floats per warp
#define ATTN_SMEM ((PS_OFF + 8 * PWARP) * 4)   // 106496 bytes

__global__ void __launch_bounds__(256, 2) attn_mma(const float* __restrict__ Qg,
                                                   const float* __restrict__ Kg,
                                                   const float* __restrict__ Vg,
                                                   float* __restrict__ Og) {
    extern __shared__ __align__(16) float smf[];
    const uint32_t sb = (uint32_t)__cvta_generic_to_shared(smf);

    const int h   = blockIdx.y;
    const int q0  = blockIdx.x * BQ;
    const int tid = threadIdx.x;
    const int warp = tid >> 5, lane = tid & 31;
    const int g   = lane >> 2;         // 0..7
    const int tg  = lane & 3;          // 0..3
    const int hoff = h * DK;

    const int r0 = warp * 16 + g;      // global-local q row
    const int r1 = r0 + 8;

    float* Pw = smf + PS_OFF + warp * PWARP;   // warp-private P [16][PLD]

    const int ld_t  = tid >> 4;        // +16 per p
    const int ld_c4 = (tid & 15) * 4;

    auto issue_kv = [&](int t0, int buf) {
#pragma unroll
        for (int p = 0; p < 4; p++) {
            int t = ld_t + p * 16;
            const float* kp = Kg + (size_t)(t0 + t) * DMODEL + hoff + ld_c4;
            const float* vp = Vg + (size_t)(t0 + t) * DMODEL + hoff + ld_c4;
            cpa16(sb + (buf * KBUF + t * KLD + ld_c4) * 4, kp);
            cpa16(sb + (VS_OFF + buf * VBUF + t * VLD + ld_c4) * 4, vp);
        }
        CPA_COMMIT();
    };

    issue_kv(0, 0);

    // ---- Persistent Q fragments (pre-scaled by 1/8; q already tf32) ----
    uint32_t qf[8][4];
    {
        const float* qp0 = Qg + (size_t)(q0 + r0) * DMODEL + hoff;
        const float* qp1 = Qg + (size_t)(q0 + r1) * DMODEL + hoff;
#pragma unroll
        for (int ks = 0; ks < 8; ks++) {
            int kc = ks * 8 + tg;
            qf[ks][0] = __float_as_uint(qp0[kc]     * 0.125f);
            qf[ks][1] = __float_as_uint(qp1[kc]     * 0.125f);
            qf[ks][2] = __float_as_uint(qp0[kc + 4] * 0.125f);
            qf[ks][3] = __float_as_uint(qp1[kc + 4] * 0.125f);
        }
    }

    float m0 = -1e30f, m1 = -1e30f, l0 = 0.f, l1 = 0.f;
    float oacc[8][4];
#pragma unroll
    for (int nt = 0; nt < 8; nt++)
#pragma unroll
        for (int i = 0; i < 4; i++) oacc[nt][i] = 0.f;

    int buf = 0;
    for (int t0 = 0; t0 < S_LEN; t0 += BT) {
        CPA_WAIT0();
        __syncthreads();   // tile ready AND all warps done with this buffer
        if (t0 + BT < S_LEN) issue_kv(t0 + BT, buf ^ 1);

        const float* Ks = smf + buf * KBUF;
        const float* Vs = smf + VS_OFF + buf * VBUF;

        // ---- S = (Q/8) K^T : warp computes 16 x 64 ----
        float accS[8][4];
#pragma unroll
        for (int nt = 0; nt < 8; nt++)
#pragma unroll
            for (int i = 0; i < 4; i++) accS[nt][i] = 0.f;

#pragma unroll
        for (int ks = 0; ks < 8; ks++) {
            const int kb = ks * 8;
#pragma unroll
            for (int nt = 0; nt < 8; nt++) {
                int t = nt * 8 + g;
                uint32_t b[2] = { __float_as_uint(Ks[t * KLD + kb + tg]),
                                  __float_as_uint(Ks[t * KLD + kb + tg + 4]) };
                mma8(accS[nt], qf[ks], b);
            }
        }

        // ---- softmax: rows fully in-warp ----
        float mx0 = -1e30f, mx1 = -1e30f;
#pragma unroll
        for (int nt = 0; nt < 8; nt++) {
            mx0 = fmaxf(mx0, fmaxf(accS[nt][0], accS[nt][1]));
            mx1 = fmaxf(mx1, fmaxf(accS[nt][2], accS[nt][3]));
        }
        mx0 = fmaxf(mx0, __shfl_xor_sync(0xffffffffu, mx0, 1));
        mx0 = fmaxf(mx0, __shfl_xor_sync(0xffffffffu, mx0, 2));
        mx1 = fmaxf(mx1, __shfl_xor_sync(0xffffffffu, mx1, 1));
        mx1 = fmaxf(mx1, __shfl_xor_sync(0xffffffffu, mx1, 2));

        float mn0 = fmaxf(m0, mx0), mn1 = fmaxf(m1, mx1);
        float c0 = __expf(m0 - mn0), c1 = __expf(m1 - mn1);
        m0 = mn0; m1 = mn1;

        float ps0 = 0.f, ps1 = 0.f;
#pragma unroll
        for (int nt = 0; nt < 8; nt++) {
            int c = nt * 8 + 2 * tg;
            float p00 = __expf(accS[nt][0] - m0);
            float p01 = __expf(accS[nt][1] - m0);
            float p10 = __expf(accS[nt][2] - m1);
            float p11 = __expf(accS[nt][3] - m1);
            ps0 += p00 + p01; ps1 += p10 + p11;
            *(float2*)&Pw[g * PLD + c]       = make_float2(f2tf(p00), f2tf(p01));
            *(float2*)&Pw[(g + 8) * PLD + c] = make_float2(f2tf(p10), f2tf(p11));
        }
        ps0 += __shfl_xor_sync(0xffffffffu, ps0, 1);
        ps0 += __shfl_xor_sync(0xffffffffu, ps0, 2);
        ps1 += __shfl_xor_sync(0xffffffffu, ps1, 1);
        ps1 += __shfl_xor_sync(0xffffffffu, ps1, 2);

        l0 = l0 * c0 + ps0;
        l1 = l1 * c1 + ps1;
#pragma unroll
        for (int nt = 0; nt < 8; nt++) {
            oacc[nt][0] *= c0; oacc[nt][1] *= c0;
            oacc[nt][2] *= c1; oacc[nt][3] *= c1;
        }
        __syncwarp();      // P visible within warp

        // ---- O += P V : warp computes 16 x 64 over d ----
#pragma unroll
        for (int ks = 0; ks < 8; ks++) {
            const int kb = ks * 8;
            uint32_t af[4];
            af[0] = __float_as_uint(Pw[g * PLD + kb + tg]);
            af[1] = __float_as_uint(Pw[(g + 8) * PLD + kb + tg]);
            af[2] = __float_as_uint(Pw[g * PLD + kb + tg + 4]);
            af[3] = __float_as_uint(Pw[(g + 8) * PLD + kb + tg + 4]);
#pragma unroll
            for (int nt = 0; nt < 8; nt++) {
                int d = nt * 8 + g;
                uint32_t b[2] = { __float_as_uint(Vs[(kb + tg) * VLD + d]),
                                  __float_as_uint(Vs[(kb + tg + 4) * VLD + d]) };
                mma8(oacc[nt], af, b);
            }
        }
        __syncwarp();      // P reads done before next-tile writes
        buf ^= 1;
    }

    // ---- normalize + write (rounded: final GEMM consumes cvt-free) ----
    float inv0 = 1.f / l0, inv1 = 1.f / l1;
#pragma unroll
    for (int nt = 0; nt < 8; nt++) {
        int c = hoff + nt * 8 + 2 * tg;
        *(float2*)(Og + (size_t)(q0 + r0) * DMODEL + c) =
            make_float2(f2tf(oacc[nt][0] * inv0), f2tf(oacc[nt][1] * inv0));
        *(float2*)(Og + (size_t)(q0 + r1) * DMODEL + c) =
            make_float2(f2tf(oacc[nt][2] * inv1), f2tf(oacc[nt][3] * inv1));
    }
}

// ---------------------------------------------------------------------------
extern "C" void kernel_launch(void* const* d_in, const int* in_sizes, int n_in,
                              void* d_out, int out_size) {
    const float* x  = (const float*)d_in[0];
    const float* Wq = (const float*)d_in[1];
    const float* Wk = (const float*)d_in[2];
    const float* Wv = (const float*)d_in[3];
    const float* Wo = (const float*)d_in[4];
    float* out = (float*)d_out;

    float *q, *k, *v, *ao, *xr, *wr;
    cudaGetSymbolAddress((void**)&q,  g_q);
    cudaGetSymbolAddress((void**)&k,  g_k);
    cudaGetSymbolAddress((void**)&v,  g_v);
    cudaGetSymbolAddress((void**)&ao, g_ao);
    cudaGetSymbolAddress((void**)&xr, g_xr);
    cudaGetSymbolAddress((void**)&wr, g_wr);
    float* wqr = wr;
    float* wkr = wr + (size_t)DMODEL * DMODEL;
    float* wvr = wr + (size_t)2 * DMODEL * DMODEL;
    float* wor = wr + (size_t)3 * DMODEL * DMODEL;

    const int GSM = 4 * GBM * GLD * sizeof(float);   // 73728
    cudaFuncSetAttribute(gemm_nt_async<true>,
                         cudaFuncAttributeMaxDynamicSharedMemorySize, GSM);
    cudaFuncSetAttribute(gemm_nt_async<false>,
                         cudaFuncAttributeMaxDynamicSharedMemorySize, GSM);
    cudaFuncSetAttribute(attn_mma,
                         cudaFuncAttributeMaxDynamicSharedMemorySize, ATTN_SMEM);

    // tf32-round inputs once
    round4<<<(S_LEN * DMODEL / 4 + 255) / 256, 256>>>(x,  xr,  S_LEN * DMODEL / 4);
    round4<<<(DMODEL * DMODEL / 4 + 255) / 256, 256>>>(Wq, wqr, DMODEL * DMODEL / 4);
    round4<<<(DMODEL * DMODEL / 4 + 255) / 256, 256>>>(Wk, wkr, DMODEL * DMODEL / 4);
    round4<<<(DMODEL * DMODEL / 4 + 255) / 256, 256>>>(Wv, wvr, DMODEL * DMODEL / 4);
    round4<<<(DMODEL * DMODEL / 4 + 255) / 256, 256>>>(Wo, wor, DMODEL * DMODEL / 4);

    dim3 gg(DMODEL / GBN, S_LEN / GBM);  // (8, 32)
    gemm_nt_async<true><<<gg, 256, GSM>>>(xr, wqr, q, S_LEN, DMODEL, DMODEL);
    gemm_nt_async<true><<<gg, 256, GSM>>>(xr, wkr, k, S_LEN, DMODEL, DMODEL);
    gemm_nt_async<true><<<gg, 256, GSM>>>(xr, wvr, v, S_LEN, DMODEL, DMODEL);

    attn_mma<<<dim3(S_LEN / BQ, NHEADS), 256, ATTN_SMEM>>>(q, k, v, ao);

    gemm_nt_async<false><<<gg, 256, GSM>>>(ao, wor, out, S_LEN, DMODEL, DMODEL);
}